// round 4
// baseline (speedup 1.0000x reference)
#include <cuda_runtime.h>
#include <cstdint>

#define N_NODES 100000
#define N_EDGES 1600000
#define NB_SCAN 196            // ceil(100000/512)

// Persistent scratch
__device__ float g_agg[N_NODES * 64];
__device__ float g_h1 [N_NODES * 64];
__device__ int   g_degi[N_NODES];
__device__ int   g_rowptr[N_NODES + 1];
__device__ int   g_cursor[N_NODES];
__device__ int   g_esrc[N_EDGES];
__device__ int   g_bsum[NB_SCAN];

// ---------------- f32x2 helpers ----------------
__device__ __forceinline__ double ffma2(double a, double b, double c) {
    double d;
    asm("fma.rn.f32x2 %0, %1, %2, %3;" : "=d"(d) : "d"(a), "d"(b), "d"(c));
    return d;
}
__device__ __forceinline__ void unpack2(double v, float& lo, float& hi) {
    asm("mov.b64 {%0, %1}, %2;" : "=f"(lo), "=f"(hi) : "d"(v));
}

// ---------------- CSR build ----------------
__global__ void csr_zero() {
    int i = blockIdx.x * blockDim.x + threadIdx.x;
    if (i < N_NODES) g_degi[i] = 0;
}

__global__ void csr_hist(const int* __restrict__ dst) {
    int e = blockIdx.x * blockDim.x + threadIdx.x;
    if (e < N_EDGES) atomicAdd(&g_degi[dst[e]], 1);
}

__global__ void scan_block() {                       // per-block degree sums
    __shared__ int sh[512];
    int t = threadIdx.x;
    int idx = blockIdx.x * 512 + t;
    int v = (idx < N_NODES) ? g_degi[idx] : 0;
    sh[t] = v;
    __syncthreads();
    for (int off = 256; off > 0; off >>= 1) {
        if (t < off) sh[t] += sh[t + off];
        __syncthreads();
    }
    if (t == 0) g_bsum[blockIdx.x] = sh[0];
}

// rowptr + cursor; each block computes its own prefix over g_bsum
__global__ void scan_write() {
    __shared__ int sh[512];
    __shared__ int sbase;
    int t = threadIdx.x;

    // base = sum of g_bsum[0 .. blockIdx.x-1]
    int bsv = (t < blockIdx.x && t < NB_SCAN) ? g_bsum[t] : 0;
    sh[t] = bsv;
    __syncthreads();
    for (int off = 256; off > 0; off >>= 1) {
        if (t < off) sh[t] += sh[t + off];
        __syncthreads();
    }
    if (t == 0) sbase = sh[0];
    __syncthreads();

    int idx = blockIdx.x * 512 + t;
    int v = (idx < N_NODES) ? g_degi[idx] : 0;
    sh[t] = v;
    __syncthreads();
    for (int off = 1; off < 512; off <<= 1) {
        int x = (t >= off) ? sh[t - off] : 0;
        __syncthreads();
        sh[t] += x;
        __syncthreads();
    }
    int excl = sh[t] - v + sbase;
    if (idx < N_NODES) {
        g_rowptr[idx] = excl;
        g_cursor[idx] = excl;
    }
    if (blockIdx.x == 0 && t == 0) g_rowptr[N_NODES] = N_EDGES;
}

__global__ void csr_scatter(const int* __restrict__ src,
                            const int* __restrict__ dst) {
    int e = blockIdx.x * blockDim.x + threadIdx.x;
    if (e < N_EDGES) {
        int p = atomicAdd(&g_cursor[dst[e]], 1);
        g_esrc[p] = src[e];
    }
}

// ---------------- Mean aggregation via CSR gather ----------------
// One warp per node. Lanes: slot s = lane>>4 (edge slot), c = lane&15 (chunk).
// 4 edges in flight per warp (2 slots x 2-deep unroll); shfl-combine slots.
template <bool LAYER1>
__global__ void agg_csr(const float4* __restrict__ xin) {
    const float4* x4 = LAYER1 ? xin : (const float4*)g_h1;
    int n = (blockIdx.x * blockDim.x + threadIdx.x) >> 5;
    if (n >= N_NODES) return;
    int lane = threadIdx.x & 31;
    int s = lane >> 4;
    int c = lane & 15;

    int b = __ldg(&g_rowptr[n]);
    int e = __ldg(&g_rowptr[n + 1]);

    float4 a0 = make_float4(0.f, 0.f, 0.f, 0.f);
    float4 a1 = make_float4(0.f, 0.f, 0.f, 0.f);

    int i = b + s;                    // this slot: edges i, i+2, i+4, ...
    for (; i + 2 < e; i += 4) {       // 2 edges per iter for this slot
        int s0 = __ldg(&g_esrc[i]);
        int s1 = __ldg(&g_esrc[i + 2]);
        float4 v0 = __ldg(&x4[s0 * 16 + c]);
        float4 v1 = __ldg(&x4[s1 * 16 + c]);
        a0.x += v0.x; a0.y += v0.y; a0.z += v0.z; a0.w += v0.w;
        a1.x += v1.x; a1.y += v1.y; a1.z += v1.z; a1.w += v1.w;
    }
    if (i < e) {
        int s0 = __ldg(&g_esrc[i]);
        float4 v0 = __ldg(&x4[s0 * 16 + c]);
        a0.x += v0.x; a0.y += v0.y; a0.z += v0.z; a0.w += v0.w;
    }

    float4 a;
    a.x = a0.x + a1.x; a.y = a0.y + a1.y;
    a.z = a0.z + a1.z; a.w = a0.w + a1.w;
    a.x += __shfl_xor_sync(0xffffffffu, a.x, 16);
    a.y += __shfl_xor_sync(0xffffffffu, a.y, 16);
    a.z += __shfl_xor_sync(0xffffffffu, a.z, 16);
    a.w += __shfl_xor_sync(0xffffffffu, a.w, 16);

    if (s == 0) {
        int deg = e - b;
        float inv = 1.0f / (float)(deg > 0 ? deg : 1);
        float4 o = make_float4(a.x * inv, a.y * inv, a.z * inv, a.w * inv);
        ((float4*)g_agg)[n * 16 + c] = o;
    }
}

// ---------------- Fused layer GEMM ----------------
// out = act( X @ Ws^T + agg @ Wn^T + b ).
// CTA: 512 thr = 16 warps = 8 rowgroups x 2 col-halves. Tile 64x64.
// Lane owns ONE column (full k): W row in regs as 32 k-pair doubles (f32x2),
// loaded directly from global (L1/L2 resident). Both phases accumulate into
// the same acc; epilogue = lo+hi + bias (+relu). No cross-warp reduction.
template <bool LAYER1>
__global__ void __launch_bounds__(512)
sage_gemm(const float* __restrict__ Xin,
          const float* __restrict__ Wself,
          const float* __restrict__ Wneigh,
          const float* __restrict__ bias,
          float* __restrict__ outp) {
    const float* X   = LAYER1 ? Xin : (const float*)g_h1;
    float*       out = LAYER1 ? (float*)g_h1 : outp;

    __shared__ __align__(16) float sA[64 * 64];     // 16 KB A tile

    const int tid  = threadIdx.x;
    const int w    = tid >> 5;
    const int lane = tid & 31;
    const int h    = w & 1;          // col-half
    const int rg   = w >> 1;         // rowgroup: rows rg*8 .. rg*8+7
    const int row0 = blockIdx.x * 64;
    const int col  = h * 32 + lane;  // this lane's output column

    double acc[8];
#pragma unroll
    for (int r = 0; r < 8; r++) acc[r] = 0.0;

    const double2* sA2 = (const double2*)sA;   // 16 double2 per row

#pragma unroll 1
    for (int ph = 0; ph < 2; ph++) {
        if (ph) __syncthreads();     // phase-0 MAC reads of sA complete

        // Stage A tile (64 rows x 16 float4), zero-filled past N.
        const float4* S = (ph == 0) ? (const float4*)X : (const float4*)g_agg;
#pragma unroll
        for (int l = 0; l < 2; l++) {
            int i = tid + l * 512;               // 0..1023
            int r = i >> 4, f = i & 15;
            int gr = row0 + r;
            float4 v = make_float4(0.f, 0.f, 0.f, 0.f);
            if (gr < N_NODES) v = __ldg(&S[gr * 16 + f]);
            ((float4*)sA)[r * 16 + f] = v;
        }

        // W row for this lane's column, packed as k-pair doubles.
        const float* Wp = (ph == 0) ? Wself : Wneigh;
        double wreg[32];
        {
            const double2* wp = (const double2*)(Wp + col * 64);
#pragma unroll
            for (int q = 0; q < 16; q++) {
                double2 t = __ldg(&wp[q]);
                wreg[2 * q]     = t.x;
                wreg[2 * q + 1] = t.y;
            }
        }
        __syncthreads();

        // MAC: q outer, r inner -> dependency distance 16 on each acc[r].
#pragma unroll
        for (int q = 0; q < 16; q++) {
#pragma unroll
            for (int r = 0; r < 8; r++) {
                double2 a = sA2[(rg * 8 + r) * 16 + q];   // warp-uniform LDS.128
                acc[r] = ffma2(a.x, wreg[2 * q],     acc[r]);
                acc[r] = ffma2(a.y, wreg[2 * q + 1], acc[r]);
            }
        }
    }

    // Epilogue
    const float bv = __ldg(&bias[col]);
#pragma unroll
    for (int r = 0; r < 8; r++) {
        int gr = row0 + rg * 8 + r;
        if (gr < N_NODES) {
            float lo, hi;
            unpack2(acc[r], lo, hi);
            float o = lo + hi + bv;
            if (LAYER1) o = fmaxf(o, 0.f);
            out[gr * 64 + col] = o;
        }
    }
}

// ---------------- Launch ----------------
extern "C" void kernel_launch(void* const* d_in, const int* in_sizes, int n_in,
                              void* d_out, int out_size) {
    const float* in_feat = (const float*)d_in[0];
    const int*   src     = (const int*)d_in[1];
    const int*   dst     = (const int*)d_in[2];
    const float* Ws1     = (const float*)d_in[3];
    const float* Wn1     = (const float*)d_in[4];
    const float* b1      = (const float*)d_in[5];
    const float* Ws2     = (const float*)d_in[6];
    const float* Wn2     = (const float*)d_in[7];
    const float* b2      = (const float*)d_in[8];
    float*       out     = (float*)d_out;

    const int e_blocks    = (N_EDGES + 255) / 256;           // 6250
    const int agg_blocks  = (N_NODES * 32 + 255) / 256;      // 12500
    const int gemm_blocks = (N_NODES + 63) / 64;             // 1563

    // CSR build
    csr_zero<<<(N_NODES + 1023) / 1024, 1024>>>();
    csr_hist<<<e_blocks, 256>>>(dst);
    scan_block<<<NB_SCAN, 512>>>();
    scan_write<<<NB_SCAN, 512>>>();
    csr_scatter<<<e_blocks, 256>>>(src, dst);

    // Layer 1
    agg_csr<true><<<agg_blocks, 256>>>((const float4*)in_feat);
    sage_gemm<true><<<gemm_blocks, 512>>>(in_feat, Ws1, Wn1, b1, nullptr);
    // Layer 2
    agg_csr<false><<<agg_blocks, 256>>>(nullptr);
    sage_gemm<false><<<gemm_blocks, 512>>>(nullptr, Ws2, Wn2, b2, out);
}

// round 5
// speedup vs baseline: 1.6158x; 1.6158x over previous
#include <cuda_runtime.h>
#include <cstdint>

#define N_NODES 100000
#define N_EDGES 1600000
#define NB_SCAN 196            // ceil(100000/512)

// Persistent scratch
__device__ float g_agg[N_NODES * 64];
__device__ float g_h1 [N_NODES * 64];
__device__ int   g_degi[N_NODES];
__device__ int   g_rowptr[N_NODES + 1];
__device__ int   g_cursor[N_NODES];
__device__ int   g_esrc[N_EDGES];
__device__ int   g_bsum[NB_SCAN];

// ---------------- f32x2 helpers ----------------
__device__ __forceinline__ double ffma2(double a, double b, double c) {
    double d;
    asm("fma.rn.f32x2 %0, %1, %2, %3;" : "=d"(d) : "d"(a), "d"(b), "d"(c));
    return d;
}
__device__ __forceinline__ void unpack2(double v, float& lo, float& hi) {
    asm("mov.b64 {%0, %1}, %2;" : "=f"(lo), "=f"(hi) : "d"(v));
}

// ---------------- CSR build ----------------
__global__ void csr_zero() {
    int i = blockIdx.x * blockDim.x + threadIdx.x;
    if (i < N_NODES) g_degi[i] = 0;
}

__global__ void csr_hist(const int* __restrict__ dst) {
    int e = blockIdx.x * blockDim.x + threadIdx.x;
    if (e < N_EDGES) atomicAdd(&g_degi[dst[e]], 1);
}

__global__ void scan_block() {                       // per-block degree sums
    __shared__ int sh[512];
    int t = threadIdx.x;
    int idx = blockIdx.x * 512 + t;
    int v = (idx < N_NODES) ? g_degi[idx] : 0;
    sh[t] = v;
    __syncthreads();
    for (int off = 256; off > 0; off >>= 1) {
        if (t < off) sh[t] += sh[t + off];
        __syncthreads();
    }
    if (t == 0) g_bsum[blockIdx.x] = sh[0];
}

// rowptr + cursor; each block computes its own prefix over g_bsum
__global__ void scan_write() {
    __shared__ int sh[512];
    __shared__ int sbase;
    int t = threadIdx.x;

    int bsv = (t < blockIdx.x && t < NB_SCAN) ? g_bsum[t] : 0;
    sh[t] = bsv;
    __syncthreads();
    for (int off = 256; off > 0; off >>= 1) {
        if (t < off) sh[t] += sh[t + off];
        __syncthreads();
    }
    if (t == 0) sbase = sh[0];
    __syncthreads();

    int idx = blockIdx.x * 512 + t;
    int v = (idx < N_NODES) ? g_degi[idx] : 0;
    sh[t] = v;
    __syncthreads();
    for (int off = 1; off < 512; off <<= 1) {
        int x = (t >= off) ? sh[t - off] : 0;
        __syncthreads();
        sh[t] += x;
        __syncthreads();
    }
    int excl = sh[t] - v + sbase;
    if (idx < N_NODES) {
        g_rowptr[idx] = excl;
        g_cursor[idx] = excl;
    }
    if (blockIdx.x == 0 && t == 0) g_rowptr[N_NODES] = N_EDGES;
}

__global__ void csr_scatter(const int* __restrict__ src,
                            const int* __restrict__ dst) {
    int e = blockIdx.x * blockDim.x + threadIdx.x;
    if (e < N_EDGES) {
        int p = atomicAdd(&g_cursor[dst[e]], 1);
        g_esrc[p] = src[e];
    }
}

// ---------------- Mean aggregation via CSR gather (Round-3 form) ----------------
// Warp handles 2 nodes (16 lanes each); lane owns one float4 feature chunk.
template <bool LAYER1>
__global__ void agg_csr(const float4* __restrict__ xin) {
    const float4* x4 = LAYER1 ? xin : (const float4*)g_h1;
    int gw   = (blockIdx.x * blockDim.x + threadIdx.x) >> 5;
    int lane = threadIdx.x & 31;
    int n = gw * 2 + (lane >> 4);
    int c = lane & 15;
    if (n >= N_NODES) return;
    int b = __ldg(&g_rowptr[n]);
    int e = __ldg(&g_rowptr[n + 1]);
    float4 a0 = make_float4(0.f, 0.f, 0.f, 0.f);
    float4 a1 = make_float4(0.f, 0.f, 0.f, 0.f);
    int i = b;
    for (; i + 1 < e; i += 2) {
        int s0 = __ldg(&g_esrc[i]);
        int s1 = __ldg(&g_esrc[i + 1]);
        float4 v0 = __ldg(&x4[s0 * 16 + c]);
        float4 v1 = __ldg(&x4[s1 * 16 + c]);
        a0.x += v0.x; a0.y += v0.y; a0.z += v0.z; a0.w += v0.w;
        a1.x += v1.x; a1.y += v1.y; a1.z += v1.z; a1.w += v1.w;
    }
    if (i < e) {
        int s0 = __ldg(&g_esrc[i]);
        float4 v0 = __ldg(&x4[s0 * 16 + c]);
        a0.x += v0.x; a0.y += v0.y; a0.z += v0.z; a0.w += v0.w;
    }
    int deg = e - b;
    float inv = 1.0f / (float)(deg > 0 ? deg : 1);
    float4 o;
    o.x = (a0.x + a1.x) * inv;
    o.y = (a0.y + a1.y) * inv;
    o.z = (a0.z + a1.z) * inv;
    o.w = (a0.w + a1.w) * inv;
    ((float4*)g_agg)[n * 16 + c] = o;
}

// ---------------- Fused layer GEMM ----------------
// out = act( X @ Ws^T + agg @ Wn^T + b ).
// CTA: 512 thr = 16 warps = 8 rowgroups x 2 col-halves. Tile 64x64.
// W staged COALESCED into shared (pitch 68), then pulled into regs as
// k-pair f32x2 doubles. Lane owns ONE column, full k; both phases
// accumulate into the same acc; epilogue = lo+hi+bias (+relu).
#define SW_PITCH 68   // floats; 272B rows = 17x16B -> aligned double2 loads

template <bool LAYER1>
__global__ void __launch_bounds__(512)
sage_gemm(const float* __restrict__ Xin,
          const float* __restrict__ Wself,
          const float* __restrict__ Wneigh,
          const float* __restrict__ bias,
          float* __restrict__ outp) {
    const float* X   = LAYER1 ? Xin : (const float*)g_h1;
    float*       out = LAYER1 ? (float*)g_h1 : outp;

    __shared__ __align__(16) float sA[64 * 64];        // 16 KB A tile
    __shared__ __align__(16) float sW[64 * SW_PITCH];  // 17 KB W stage

    const int tid  = threadIdx.x;
    const int w    = tid >> 5;
    const int lane = tid & 31;
    const int h    = w & 1;          // col-half
    const int rg   = w >> 1;         // rowgroup: rows rg*8 .. rg*8+7
    const int row0 = blockIdx.x * 64;
    const int col  = h * 32 + lane;  // this lane's output column

    double acc[8];
#pragma unroll
    for (int r = 0; r < 8; r++) acc[r] = 0.0;

    const double2* sA2 = (const double2*)sA;   // 16 double2 per row

#pragma unroll 1
    for (int ph = 0; ph < 2; ph++) {
        if (ph) __syncthreads();     // phase-0 reads of sA/sW complete

        // Stage W coalesced: thread i loads Wp[i], i = j*64+k.
        const float* Wp = (ph == 0) ? Wself : Wneigh;
#pragma unroll
        for (int l = 0; l < 8; l++) {
            int i = tid + l * 512;               // 0..4095
            int j = i >> 6, k = i & 63;
            sW[j * SW_PITCH + k] = __ldg(&Wp[i]);
        }

        // Stage A tile (64 rows x 16 float4), zero-filled past N.
        const float4* S = (ph == 0) ? (const float4*)X : (const float4*)g_agg;
#pragma unroll
        for (int l = 0; l < 2; l++) {
            int i = tid + l * 512;               // 0..1023
            int r = i >> 4, f = i & 15;
            int gr = row0 + r;
            float4 v = make_float4(0.f, 0.f, 0.f, 0.f);
            if (gr < N_NODES) v = __ldg(&S[gr * 16 + f]);
            ((float4*)sA)[r * 16 + f] = v;
        }
        __syncthreads();

        // Pull this lane's W row (k-pair packed doubles) from shared.
        double wreg[32];
        {
            const double2* wp = (const double2*)(sW + col * SW_PITCH);
#pragma unroll
            for (int q = 0; q < 16; q++) {
                double2 t = wp[q];
                wreg[2 * q]     = t.x;
                wreg[2 * q + 1] = t.y;
            }
        }

        // MAC: q outer, r inner -> dep distance 16 on each acc[r].
#pragma unroll
        for (int q = 0; q < 16; q++) {
#pragma unroll
            for (int r = 0; r < 8; r++) {
                double2 a = sA2[(rg * 8 + r) * 16 + q];   // warp-uniform LDS.128
                acc[r] = ffma2(a.x, wreg[2 * q],     acc[r]);
                acc[r] = ffma2(a.y, wreg[2 * q + 1], acc[r]);
            }
        }
    }

    // Epilogue
    const float bv = __ldg(&bias[col]);
#pragma unroll
    for (int r = 0; r < 8; r++) {
        int gr = row0 + rg * 8 + r;
        if (gr < N_NODES) {
            float lo, hi;
            unpack2(acc[r], lo, hi);
            float o = lo + hi + bv;
            if (LAYER1) o = fmaxf(o, 0.f);
            out[gr * 64 + col] = o;
        }
    }
}

// ---------------- Launch ----------------
extern "C" void kernel_launch(void* const* d_in, const int* in_sizes, int n_in,
                              void* d_out, int out_size) {
    const float* in_feat = (const float*)d_in[0];
    const int*   src     = (const int*)d_in[1];
    const int*   dst     = (const int*)d_in[2];
    const float* Ws1     = (const float*)d_in[3];
    const float* Wn1     = (const float*)d_in[4];
    const float* b1      = (const float*)d_in[5];
    const float* Ws2     = (const float*)d_in[6];
    const float* Wn2     = (const float*)d_in[7];
    const float* b2      = (const float*)d_in[8];
    float*       out     = (float*)d_out;

    const int e_blocks    = (N_EDGES + 255) / 256;                 // 6250
    const int agg_blocks  = ((N_NODES + 1) / 2 * 32 + 255) / 256;  // 6250
    const int gemm_blocks = (N_NODES + 63) / 64;                   // 1563

    // CSR build
    csr_zero<<<(N_NODES + 1023) / 1024, 1024>>>();
    csr_hist<<<e_blocks, 256>>>(dst);
    scan_block<<<NB_SCAN, 512>>>();
    scan_write<<<NB_SCAN, 512>>>();
    csr_scatter<<<e_blocks, 256>>>(src, dst);

    // Layer 1
    agg_csr<true><<<agg_blocks, 256>>>((const float4*)in_feat);
    sage_gemm<true><<<gemm_blocks, 512>>>(in_feat, Ws1, Wn1, b1, nullptr);
    // Layer 2
    agg_csr<false><<<agg_blocks, 256>>>(nullptr);
    sage_gemm<false><<<gemm_blocks, 512>>>(nullptr, Ws2, Wn2, b2, out);
}

// round 6
// speedup vs baseline: 1.6666x; 1.0314x over previous
#include <cuda_runtime.h>
#include <cstdint>

#define N_NODES 100000
#define N_EDGES 1600000
#define NB_SCAN 196            // ceil(100000/512)

// Persistent scratch
__device__ float g_h1 [N_NODES * 64];
__device__ int   g_degi[N_NODES];
__device__ int   g_rowptr[N_NODES + 1];
__device__ int   g_cursor[N_NODES];
__device__ int   g_esrc[N_EDGES];
__device__ int   g_bsum[NB_SCAN];

// ---------------- f32x2 helpers ----------------
__device__ __forceinline__ double ffma2(double a, double b, double c) {
    double d;
    asm("fma.rn.f32x2 %0, %1, %2, %3;" : "=d"(d) : "d"(a), "d"(b), "d"(c));
    return d;
}
__device__ __forceinline__ void unpack2(double v, float& lo, float& hi) {
    asm("mov.b64 {%0, %1}, %2;" : "=f"(lo), "=f"(hi) : "d"(v));
}

// ---------------- CSR build ----------------
__global__ void csr_zero() {
    int i = blockIdx.x * blockDim.x + threadIdx.x;
    if (i < N_NODES) g_degi[i] = 0;
}

__global__ void csr_hist(const int* __restrict__ dst) {
    int e = blockIdx.x * blockDim.x + threadIdx.x;
    if (e < N_EDGES) atomicAdd(&g_degi[dst[e]], 1);
}

__global__ void scan_block() {                       // per-block degree sums
    __shared__ int sh[512];
    int t = threadIdx.x;
    int idx = blockIdx.x * 512 + t;
    int v = (idx < N_NODES) ? g_degi[idx] : 0;
    sh[t] = v;
    __syncthreads();
    for (int off = 256; off > 0; off >>= 1) {
        if (t < off) sh[t] += sh[t + off];
        __syncthreads();
    }
    if (t == 0) g_bsum[blockIdx.x] = sh[0];
}

// rowptr + cursor; each block computes its own prefix over g_bsum
__global__ void scan_write() {
    __shared__ int sh[512];
    __shared__ int sbase;
    int t = threadIdx.x;

    int bsv = (t < blockIdx.x && t < NB_SCAN) ? g_bsum[t] : 0;
    sh[t] = bsv;
    __syncthreads();
    for (int off = 256; off > 0; off >>= 1) {
        if (t < off) sh[t] += sh[t + off];
        __syncthreads();
    }
    if (t == 0) sbase = sh[0];
    __syncthreads();

    int idx = blockIdx.x * 512 + t;
    int v = (idx < N_NODES) ? g_degi[idx] : 0;
    sh[t] = v;
    __syncthreads();
    for (int off = 1; off < 512; off <<= 1) {
        int x = (t >= off) ? sh[t - off] : 0;
        __syncthreads();
        sh[t] += x;
        __syncthreads();
    }
    int excl = sh[t] - v + sbase;
    if (idx < N_NODES) {
        g_rowptr[idx] = excl;
        g_cursor[idx] = excl;
    }
    if (blockIdx.x == 0 && t == 0) g_rowptr[N_NODES] = N_EDGES;
}

__global__ void csr_scatter(const int* __restrict__ src,
                            const int* __restrict__ dst) {
    int e = blockIdx.x * blockDim.x + threadIdx.x;
    if (e < N_EDGES) {
        int p = atomicAdd(&g_cursor[dst[e]], 1);
        g_esrc[p] = src[e];
    }
}

// ---------------- Fused layer: gather-mean + dual GEMM ----------------
// out = act( X @ Ws^T + mean_neigh(X) @ Wn^T + b )
// CTA: 512 thr, 64 rows x 64 cols. Dynamic smem layout:
//   sA  [64*64]f  self tile
//   sN  [64*64]f  gathered neighbor-mean tile
//   sWs [64*66]f  Wself staged (pitch 66 -> conflict-free 8B lane reads)
//   sWn [64*66]f  Wneigh staged
// One __syncthreads between (stage+gather) and MAC.
#define SWP 66
#define SM_A  0
#define SM_N  (64 * 64)
#define SM_WS (2 * 64 * 64)
#define SM_WN (2 * 64 * 64 + 64 * SWP)
#define SMEM_FLOATS (2 * 64 * 64 + 2 * 64 * SWP)
#define SMEM_BYTES  (SMEM_FLOATS * 4)          // 66560

template <bool LAYER1>
__global__ void __launch_bounds__(512)
sage_fused(const float* __restrict__ Xin,
           const float* __restrict__ Wself,
           const float* __restrict__ Wneigh,
           const float* __restrict__ bias,
           float* __restrict__ outp) {
    const float* X   = LAYER1 ? Xin : (const float*)g_h1;
    float*       out = LAYER1 ? (float*)g_h1 : outp;

    extern __shared__ __align__(16) float sm[];
    float* sA  = sm + SM_A;
    float* sN  = sm + SM_N;
    float* sWs = sm + SM_WS;
    float* sWn = sm + SM_WN;

    const int tid  = threadIdx.x;
    const int w    = tid >> 5;
    const int lane = tid & 31;
    const int h    = w & 1;          // col-half
    const int rg   = w >> 1;         // rowgroup: rows rg*8 .. rg*8+7
    const int row0 = blockIdx.x * 64;
    const int col  = h * 32 + lane;  // this lane's output column

    // ---- Stage both W matrices (coalesced; pitch 66) ----
#pragma unroll
    for (int l = 0; l < 8; l++) {
        int i = tid + l * 512;               // 0..4095
        int j = i >> 6, k = i & 63;
        sWs[j * SWP + k] = __ldg(&Wself[i]);
        sWn[j * SWP + k] = __ldg(&Wneigh[i]);
    }

    // ---- Stage self tile sA (64 rows x 16 float4) ----
    const float4* X4 = (const float4*)X;
#pragma unroll
    for (int l = 0; l < 2; l++) {
        int i = tid + l * 512;               // 0..1023
        int r = i >> 4, f = i & 15;
        int gr = row0 + r;
        float4 v = make_float4(0.f, 0.f, 0.f, 0.f);
        if (gr < N_NODES) v = __ldg(&X4[gr * 16 + f]);
        ((float4*)sA)[r * 16 + f] = v;
    }

    // ---- Gather-mean into sN: warp handles 4 nodes (2 pairs of 16 lanes) ----
    {
        int s = lane >> 4;
        int c = lane & 15;
#pragma unroll 1
        for (int p = 0; p < 2; p++) {
            int nl = (w << 2) + (p << 1) + s;     // local node 0..63
            int n = row0 + nl;
            float4 a0 = make_float4(0.f, 0.f, 0.f, 0.f);
            float4 a1 = make_float4(0.f, 0.f, 0.f, 0.f);
            int deg = 0;
            if (n < N_NODES) {
                int b = __ldg(&g_rowptr[n]);
                int e = __ldg(&g_rowptr[n + 1]);
                deg = e - b;
                int i = b;
                for (; i + 1 < e; i += 2) {
                    int s0 = __ldg(&g_esrc[i]);
                    int s1 = __ldg(&g_esrc[i + 1]);
                    float4 v0 = __ldg(&X4[s0 * 16 + c]);
                    float4 v1 = __ldg(&X4[s1 * 16 + c]);
                    a0.x += v0.x; a0.y += v0.y; a0.z += v0.z; a0.w += v0.w;
                    a1.x += v1.x; a1.y += v1.y; a1.z += v1.z; a1.w += v1.w;
                }
                if (i < e) {
                    int s0 = __ldg(&g_esrc[i]);
                    float4 v0 = __ldg(&X4[s0 * 16 + c]);
                    a0.x += v0.x; a0.y += v0.y; a0.z += v0.z; a0.w += v0.w;
                }
            }
            float inv = 1.0f / (float)(deg > 0 ? deg : 1);
            float4 o;
            o.x = (a0.x + a1.x) * inv;
            o.y = (a0.y + a1.y) * inv;
            o.z = (a0.z + a1.z) * inv;
            o.w = (a0.w + a1.w) * inv;
            ((float4*)sN)[nl * 16 + c] = o;
        }
    }

    __syncthreads();   // the only CTA-wide sync

    // ---- MAC: self phase then neigh phase, same accumulators ----
    double acc[8];
#pragma unroll
    for (int r = 0; r < 8; r++) acc[r] = 0.0;

    {
        // wreg[i] = k-pair i of W[col][*]  (pitch 66 -> 8B aligned, bank-free)
        double wreg[32];
        const double* wp = (const double*)(sWs + col * SWP);
#pragma unroll
        for (int q = 0; q < 32; q++) wreg[q] = wp[q];

        const double2* t2 = (const double2*)sA;
#pragma unroll
        for (int q = 0; q < 16; q++) {
#pragma unroll
            for (int r = 0; r < 8; r++) {
                double2 a = t2[(rg * 8 + r) * 16 + q];   // warp-uniform LDS.128
                acc[r] = ffma2(a.x, wreg[2 * q],     acc[r]);
                acc[r] = ffma2(a.y, wreg[2 * q + 1], acc[r]);
            }
        }
    }
    {
        double wreg[32];
        const double* wp = (const double*)(sWn + col * SWP);
#pragma unroll
        for (int q = 0; q < 32; q++) wreg[q] = wp[q];

        const double2* t2 = (const double2*)sN;
#pragma unroll
        for (int q = 0; q < 16; q++) {
#pragma unroll
            for (int r = 0; r < 8; r++) {
                double2 a = t2[(rg * 8 + r) * 16 + q];
                acc[r] = ffma2(a.x, wreg[2 * q],     acc[r]);
                acc[r] = ffma2(a.y, wreg[2 * q + 1], acc[r]);
            }
        }
    }

    // ---- Epilogue ----
    const float bv = __ldg(&bias[col]);
#pragma unroll
    for (int r = 0; r < 8; r++) {
        int gr = row0 + rg * 8 + r;
        if (gr < N_NODES) {
            float lo, hi;
            unpack2(acc[r], lo, hi);
            float o = lo + hi + bv;
            if (LAYER1) o = fmaxf(o, 0.f);
            out[gr * 64 + col] = o;
        }
    }
}

// ---------------- Launch ----------------
extern "C" void kernel_launch(void* const* d_in, const int* in_sizes, int n_in,
                              void* d_out, int out_size) {
    const float* in_feat = (const float*)d_in[0];
    const int*   src     = (const int*)d_in[1];
    const int*   dst     = (const int*)d_in[2];
    const float* Ws1     = (const float*)d_in[3];
    const float* Wn1     = (const float*)d_in[4];
    const float* b1      = (const float*)d_in[5];
    const float* Ws2     = (const float*)d_in[6];
    const float* Wn2     = (const float*)d_in[7];
    const float* b2      = (const float*)d_in[8];
    float*       out     = (float*)d_out;

    // Opt-in to >48KB dynamic shared (host-side attr; not captured; idempotent)
    cudaFuncSetAttribute(sage_fused<true>,
                         cudaFuncAttributeMaxDynamicSharedMemorySize, SMEM_BYTES);
    cudaFuncSetAttribute(sage_fused<false>,
                         cudaFuncAttributeMaxDynamicSharedMemorySize, SMEM_BYTES);

    const int e_blocks    = (N_EDGES + 255) / 256;   // 6250
    const int fuse_blocks = (N_NODES + 63) / 64;     // 1563

    // CSR build
    csr_zero<<<(N_NODES + 1023) / 1024, 1024>>>();
    csr_hist<<<e_blocks, 256>>>(dst);
    scan_block<<<NB_SCAN, 512>>>();
    scan_write<<<NB_SCAN, 512>>>();
    csr_scatter<<<e_blocks, 256>>>(src, dst);

    // Fused layers
    sage_fused<true><<<fuse_blocks, 512, SMEM_BYTES>>>(in_feat, Ws1, Wn1, b1, nullptr);
    sage_fused<false><<<fuse_blocks, 512, SMEM_BYTES>>>(nullptr, Ws2, Wn2, b2, out);
}

// round 7
// speedup vs baseline: 1.8329x; 1.0998x over previous
#include <cuda_runtime.h>
#include <cuda_fp16.h>
#include <cstdint>

#define N_NODES 100000
#define N_EDGES 1600000
#define NB_SCAN 196            // ceil(100000/512)

// Persistent scratch (zero-initialized at module load; scatter re-zeros
// g_degi/g_bsum each call so every graph replay sees the same state).
__device__ float  g_h1 [N_NODES * 64];
__device__ __half g_xh [N_NODES * 64];   // fp16 mirror of in_feat
__device__ __half g_h1h[N_NODES * 64];   // fp16 mirror of h1
__device__ int    g_degi[N_NODES];
__device__ int    g_rowptr[N_NODES + 1];
__device__ int    g_cursor[N_NODES];
__device__ int    g_esrc[N_EDGES];
__device__ int    g_bsum[NB_SCAN];

// ---------------- helpers ----------------
__device__ __forceinline__ double ffma2(double a, double b, double c) {
    double d;
    asm("fma.rn.f32x2 %0, %1, %2, %3;" : "=d"(d) : "d"(a), "d"(b), "d"(c));
    return d;
}
__device__ __forceinline__ void unpack2(double v, float& lo, float& hi) {
    asm("mov.b64 {%0, %1}, %2;" : "=f"(lo), "=f"(hi) : "d"(v));
}
__device__ __forceinline__ void st_release(int* p, int v) {
    asm volatile("st.release.gpu.b32 [%0], %1;" :: "l"(p), "r"(v) : "memory");
}
__device__ __forceinline__ int ld_acquire(const int* p) {
    int v;
    asm volatile("ld.acquire.gpu.b32 %0, [%1];" : "=r"(v) : "l"(p) : "memory");
    return v;
}

// ---------------- CSR build ----------------
// (0) histogram + fp16 cast of in_feat (thread e covers edge e AND float4 e;
//     both counts are exactly 1.6M).
__global__ void csr_hist_cast(const int* __restrict__ dst,
                              const float4* __restrict__ xin) {
    int e = blockIdx.x * blockDim.x + threadIdx.x;
    if (e < N_EDGES) {
        atomicAdd(&g_degi[dst[e]], 1);
        float4 v = __ldg(&xin[e]);
        __half2* xh2 = (__half2*)g_xh;
        xh2[2 * e]     = __floats2half2_rn(v.x, v.y);
        xh2[2 * e + 1] = __floats2half2_rn(v.z, v.w);
    }
}

// (1) single-pass scan with lookback: rowptr + cursor in one launch.
// g_bsum starts zeroed; block publishes total+1 (release), predecessors
// spin with acquire loads. 196 blocks of 512 all resident -> no deadlock.
__global__ void scan_lookback() {
    __shared__ int sh[512];
    int t = threadIdx.x, bid = blockIdx.x;
    int idx = bid * 512 + t;
    int v = (idx < N_NODES) ? g_degi[idx] : 0;

    sh[t] = v;
    __syncthreads();
    for (int off = 1; off < 512; off <<= 1) {
        int x = (t >= off) ? sh[t - off] : 0;
        __syncthreads();
        sh[t] += x;
        __syncthreads();
    }
    int incl = sh[t];
    int btot = sh[511];
    if (t == 0) st_release(&g_bsum[bid], btot + 1);

    int pre = 0;
    if (t < bid) {
        int x;
        do { x = ld_acquire(&g_bsum[t]); } while (x == 0);
        pre = x - 1;
    }
    __syncthreads();
    sh[t] = pre;
    __syncthreads();
    for (int off = 256; off > 0; off >>= 1) {
        if (t < off) sh[t] += sh[t + off];
        __syncthreads();
    }
    int excl = incl - v + sh[0];
    if (idx < N_NODES) {
        g_rowptr[idx] = excl;
        g_cursor[idx] = excl;
    }
    if (bid == 0 && t == 0) g_rowptr[N_NODES] = N_EDGES;
}

// (2) scatter edges into CSR; also reset degi/bsum for the next replay.
__global__ void csr_scatter(const int* __restrict__ src,
                            const int* __restrict__ dst) {
    int e = blockIdx.x * blockDim.x + threadIdx.x;
    if (e < N_EDGES) {
        int p = atomicAdd(&g_cursor[dst[e]], 1);
        g_esrc[p] = src[e];
    }
    if (e < N_NODES) g_degi[e] = 0;
    if (e < NB_SCAN) g_bsum[e] = 0;
}

// ---------------- Fused layer: fp16 gather-mean + dual f32x2 GEMM ----------------
// out = act( X @ Ws^T + mean_neigh(Xh) @ Wn^T + b )
#define SWP 66
#define SM_A  0
#define SM_N  (64 * 64)
#define SM_WS (2 * 64 * 64)
#define SM_WN (2 * 64 * 64 + 64 * SWP)
#define SMEM_FLOATS (2 * 64 * 64 + 2 * 64 * SWP)
#define SMEM_BYTES  (SMEM_FLOATS * 4)          // 66560

template <bool LAYER1>
__global__ void __launch_bounds__(512)
sage_fused(const float* __restrict__ Xin,
           const float* __restrict__ Wself,
           const float* __restrict__ Wneigh,
           const float* __restrict__ bias,
           float* __restrict__ outp) {
    const float* X   = LAYER1 ? Xin : (const float*)g_h1;
    float*       out = LAYER1 ? (float*)g_h1 : outp;
    const uint4* H   = LAYER1 ? (const uint4*)g_xh : (const uint4*)g_h1h;

    extern __shared__ __align__(16) float sm[];
    float* sA  = sm + SM_A;
    float* sN  = sm + SM_N;
    float* sWs = sm + SM_WS;
    float* sWn = sm + SM_WN;

    const int tid  = threadIdx.x;
    const int w    = tid >> 5;
    const int lane = tid & 31;
    const int h    = w & 1;          // col-half
    const int rg   = w >> 1;         // rowgroup: rows rg*8 .. rg*8+7
    const int row0 = blockIdx.x * 64;
    const int col  = h * 32 + lane;  // this lane's output column

    // ---- Stage both W matrices (coalesced; pitch 66) ----
#pragma unroll
    for (int l = 0; l < 8; l++) {
        int i = tid + l * 512;               // 0..4095
        int j = i >> 6, k = i & 63;
        sWs[j * SWP + k] = __ldg(&Wself[i]);
        sWn[j * SWP + k] = __ldg(&Wneigh[i]);
    }

    // ---- Stage self tile sA (fp32, 64 rows x 16 float4) ----
    const float4* X4 = (const float4*)X;
#pragma unroll
    for (int l = 0; l < 2; l++) {
        int i = tid + l * 512;               // 0..1023
        int r = i >> 4, f = i & 15;
        int gr = row0 + r;
        float4 v = make_float4(0.f, 0.f, 0.f, 0.f);
        if (gr < N_NODES) v = __ldg(&X4[gr * 16 + f]);
        ((float4*)sA)[r * 16 + f] = v;
    }

    // ---- Gather-mean (fp16 rows, 128B = 1 line/edge) ----
    // 8 lanes per node -> 4 nodes concurrently per warp; 2 edges in flight.
    {
        int g = lane >> 3;                // node group 0..3
        int c = lane & 7;                 // uint4 chunk (8 halfs)
        int nl = w * 4 + g;               // local node 0..63
        int n = row0 + nl;

        float2 a0[4], a1[4];
#pragma unroll
        for (int j = 0; j < 4; j++) {
            a0[j] = make_float2(0.f, 0.f);
            a1[j] = make_float2(0.f, 0.f);
        }
        int deg = 0;
        if (n < N_NODES) {
            int b = __ldg(&g_rowptr[n]);
            int e = __ldg(&g_rowptr[n + 1]);
            deg = e - b;
            int i = b;
            for (; i + 1 < e; i += 2) {
                int s0 = __ldg(&g_esrc[i]);
                int s1 = __ldg(&g_esrc[i + 1]);
                uint4 v0 = __ldg(&H[s0 * 8 + c]);
                uint4 v1 = __ldg(&H[s1 * 8 + c]);
                const __half2* p0 = (const __half2*)&v0;
                const __half2* p1 = (const __half2*)&v1;
#pragma unroll
                for (int j = 0; j < 4; j++) {
                    float2 f0 = __half22float2(p0[j]);
                    float2 f1 = __half22float2(p1[j]);
                    a0[j].x += f0.x; a0[j].y += f0.y;
                    a1[j].x += f1.x; a1[j].y += f1.y;
                }
            }
            if (i < e) {
                int s0 = __ldg(&g_esrc[i]);
                uint4 v0 = __ldg(&H[s0 * 8 + c]);
                const __half2* p0 = (const __half2*)&v0;
#pragma unroll
                for (int j = 0; j < 4; j++) {
                    float2 f0 = __half22float2(p0[j]);
                    a0[j].x += f0.x; a0[j].y += f0.y;
                }
            }
        }
        float inv = 1.0f / (float)(deg > 0 ? deg : 1);
        float s[8];
#pragma unroll
        for (int j = 0; j < 4; j++) {
            s[2 * j]     = (a0[j].x + a1[j].x) * inv;
            s[2 * j + 1] = (a0[j].y + a1[j].y) * inv;
        }
        float4* np = (float4*)(sN + nl * 64 + c * 8);
        np[0] = make_float4(s[0], s[1], s[2], s[3]);
        np[1] = make_float4(s[4], s[5], s[6], s[7]);
    }

    __syncthreads();   // the only CTA-wide sync

    // ---- MAC: self phase then neigh phase, same accumulators ----
    double acc[8];
#pragma unroll
    for (int r = 0; r < 8; r++) acc[r] = 0.0;

    {
        double wreg[32];
        const double* wp = (const double*)(sWs + col * SWP);
#pragma unroll
        for (int q = 0; q < 32; q++) wreg[q] = wp[q];

        const double2* t2 = (const double2*)sA;
#pragma unroll
        for (int q = 0; q < 16; q++) {
#pragma unroll
            for (int r = 0; r < 8; r++) {
                double2 a = t2[(rg * 8 + r) * 16 + q];   // warp-uniform LDS.128
                acc[r] = ffma2(a.x, wreg[2 * q],     acc[r]);
                acc[r] = ffma2(a.y, wreg[2 * q + 1], acc[r]);
            }
        }
    }
    {
        double wreg[32];
        const double* wp = (const double*)(sWn + col * SWP);
#pragma unroll
        for (int q = 0; q < 32; q++) wreg[q] = wp[q];

        const double2* t2 = (const double2*)sN;
#pragma unroll
        for (int q = 0; q < 16; q++) {
#pragma unroll
            for (int r = 0; r < 8; r++) {
                double2 a = t2[(rg * 8 + r) * 16 + q];
                acc[r] = ffma2(a.x, wreg[2 * q],     acc[r]);
                acc[r] = ffma2(a.y, wreg[2 * q + 1], acc[r]);
            }
        }
    }

    // ---- Epilogue: bias (+relu); layer 1 also emits the fp16 mirror ----
    const float bv = __ldg(&bias[col]);
#pragma unroll
    for (int r = 0; r < 8; r++) {
        int gr = row0 + rg * 8 + r;
        if (gr < N_NODES) {
            float lo, hi;
            unpack2(acc[r], lo, hi);
            float o = lo + hi + bv;
            if (LAYER1) {
                o = fmaxf(o, 0.f);
                g_h1h[gr * 64 + col] = __float2half_rn(o);
            }
            out[gr * 64 + col] = o;
        }
    }
}

// ---------------- Launch ----------------
extern "C" void kernel_launch(void* const* d_in, const int* in_sizes, int n_in,
                              void* d_out, int out_size) {
    const float* in_feat = (const float*)d_in[0];
    const int*   src     = (const int*)d_in[1];
    const int*   dst     = (const int*)d_in[2];
    const float* Ws1     = (const float*)d_in[3];
    const float* Wn1     = (const float*)d_in[4];
    const float* b1      = (const float*)d_in[5];
    const float* Ws2     = (const float*)d_in[6];
    const float* Wn2     = (const float*)d_in[7];
    const float* b2      = (const float*)d_in[8];
    float*       out     = (float*)d_out;

    cudaFuncSetAttribute(sage_fused<true>,
                         cudaFuncAttributeMaxDynamicSharedMemorySize, SMEM_BYTES);
    cudaFuncSetAttribute(sage_fused<false>,
                         cudaFuncAttributeMaxDynamicSharedMemorySize, SMEM_BYTES);

    const int e_blocks    = (N_EDGES + 255) / 256;   // 6250
    const int fuse_blocks = (N_NODES + 63) / 64;     // 1563

    csr_hist_cast<<<e_blocks, 256>>>(dst, (const float4*)in_feat);   // 0
    scan_lookback<<<NB_SCAN, 512>>>();                               // 1
    csr_scatter<<<e_blocks, 256>>>(src, dst);                        // 2
    sage_fused<true><<<fuse_blocks, 512, SMEM_BYTES>>>(in_feat, Ws1, Wn1, b1, nullptr);  // 3 (profiled)
    sage_fused<false><<<fuse_blocks, 512, SMEM_BYTES>>>(nullptr, Ws2, Wn2, b2, out);     // 4
}

// round 9
// speedup vs baseline: 1.8499x; 1.0093x over previous
#include <cuda_runtime.h>
#include <cuda_fp16.h>
#include <cstdint>

#define N_NODES 100000
#define N_EDGES 1600000
#define NB_SCAN 196            // ceil(100000/512)

// Persistent scratch (zero-initialized at module load; scatter re-zeros
// g_degi/g_bsum each call so every graph replay sees the same state).
__device__ float  g_h1 [N_NODES * 64];
__device__ __half g_xh [N_NODES * 64];   // fp16 mirror of in_feat
__device__ __half g_h1h[N_NODES * 64];   // fp16 mirror of h1
__device__ int    g_degi[N_NODES];
__device__ int    g_rowptr[N_NODES + 1];
__device__ int    g_cursor[N_NODES];
__device__ int    g_esrc[N_EDGES];
__device__ int    g_bsum[NB_SCAN];

// ---------------- helpers ----------------
__device__ __forceinline__ double ffma2(double a, double b, double c) {
    double d;
    asm("fma.rn.f32x2 %0, %1, %2, %3;" : "=d"(d) : "d"(a), "d"(b), "d"(c));
    return d;
}
__device__ __forceinline__ void unpack2(double v, float& lo, float& hi) {
    asm("mov.b64 {%0, %1}, %2;" : "=f"(lo), "=f"(hi) : "d"(v));
}
__device__ __forceinline__ void st_release(int* p, int v) {
    asm volatile("st.release.gpu.b32 [%0], %1;" :: "l"(p), "r"(v) : "memory");
}
__device__ __forceinline__ int ld_acquire(const int* p) {
    int v;
    asm volatile("ld.acquire.gpu.b32 %0, [%1];" : "=r"(v) : "l"(p) : "memory");
    return v;
}

// ---------------- CSR build ----------------
// (0) histogram + fp16 cast of in_feat.
__global__ void csr_hist_cast(const int* __restrict__ dst,
                              const float4* __restrict__ xin) {
    int e = blockIdx.x * blockDim.x + threadIdx.x;
    if (e < N_EDGES) {
        atomicAdd(&g_degi[dst[e]], 1);
        float4 v = __ldg(&xin[e]);
        __half2* xh2 = (__half2*)g_xh;
        xh2[2 * e]     = __floats2half2_rn(v.x, v.y);
        xh2[2 * e + 1] = __floats2half2_rn(v.z, v.w);
    }
}

// (1) single-pass scan with lookback.
__global__ void scan_lookback() {
    __shared__ int sh[512];
    int t = threadIdx.x, bid = blockIdx.x;
    int idx = bid * 512 + t;
    int v = (idx < N_NODES) ? g_degi[idx] : 0;

    sh[t] = v;
    __syncthreads();
    for (int off = 1; off < 512; off <<= 1) {
        int x = (t >= off) ? sh[t - off] : 0;
        __syncthreads();
        sh[t] += x;
        __syncthreads();
    }
    int incl = sh[t];
    int btot = sh[511];
    if (t == 0) st_release(&g_bsum[bid], btot + 1);

    int pre = 0;
    if (t < bid) {
        int x;
        do { x = ld_acquire(&g_bsum[t]); } while (x == 0);
        pre = x - 1;
    }
    __syncthreads();
    sh[t] = pre;
    __syncthreads();
    for (int off = 256; off > 0; off >>= 1) {
        if (t < off) sh[t] += sh[t + off];
        __syncthreads();
    }
    int excl = incl - v + sh[0];
    if (idx < N_NODES) {
        g_rowptr[idx] = excl;
        g_cursor[idx] = excl;
    }
    if (bid == 0 && t == 0) g_rowptr[N_NODES] = N_EDGES;
}

// (2) scatter + reset degi/bsum for next replay.
__global__ void csr_scatter(const int* __restrict__ src,
                            const int* __restrict__ dst) {
    int e = blockIdx.x * blockDim.x + threadIdx.x;
    if (e < N_EDGES) {
        int p = atomicAdd(&g_cursor[dst[e]], 1);
        g_esrc[p] = src[e];
    }
    if (e < N_NODES) g_degi[e] = 0;
    if (e < NB_SCAN) g_bsum[e] = 0;
}

// ---------------- Fused layer: fp16 gather-mean + dual f32x2 GEMM ----------------
// out = act( X @ Ws^T + mean_neigh(Xh) @ Wn^T + b )
// MAC layout: warp w owns rows w*4..w*4+3; lane owns cols {lane, lane+32}.
// Per k-quad: 2 W LDS.128 + 4 uniform A LDS.128 -> 16 FFMA2.
// SWP = 68 floats = 272B rows: 16B-aligned row bases (double2-safe) AND
// conflict-free within each 8-lane phase (banks 4*lane mod 32 distinct).
#define SWP 68
#define SM_A  0
#define SM_N  (64 * 64)
#define SM_WS (2 * 64 * 64)
#define SM_WN (2 * 64 * 64 + 64 * SWP)
#define SMEM_FLOATS (2 * 64 * 64 + 2 * 64 * SWP)
#define SMEM_BYTES  (SMEM_FLOATS * 4)          // 67584

template <bool LAYER1>
__global__ void __launch_bounds__(512)
sage_fused(const float* __restrict__ Xin,
           const float* __restrict__ Wself,
           const float* __restrict__ Wneigh,
           const float* __restrict__ bias,
           float* __restrict__ outp) {
    const float* X   = LAYER1 ? Xin : (const float*)g_h1;
    float*       out = LAYER1 ? (float*)g_h1 : outp;
    const uint4* H   = LAYER1 ? (const uint4*)g_xh : (const uint4*)g_h1h;

    extern __shared__ __align__(16) float sm[];
    float* sA  = sm + SM_A;
    float* sN  = sm + SM_N;
    float* sWs = sm + SM_WS;
    float* sWn = sm + SM_WN;

    const int tid  = threadIdx.x;
    const int w    = tid >> 5;
    const int lane = tid & 31;
    const int row0 = blockIdx.x * 64;

    // ---- Stage both W matrices (coalesced; pitch 68) ----
#pragma unroll
    for (int l = 0; l < 8; l++) {
        int i = tid + l * 512;               // 0..4095
        int j = i >> 6, k = i & 63;
        sWs[j * SWP + k] = __ldg(&Wself[i]);
        sWn[j * SWP + k] = __ldg(&Wneigh[i]);
    }

    // ---- Stage self tile sA (fp32, 64 rows x 16 float4) ----
    const float4* X4 = (const float4*)X;
#pragma unroll
    for (int l = 0; l < 2; l++) {
        int i = tid + l * 512;               // 0..1023
        int r = i >> 4, f = i & 15;
        int gr = row0 + r;
        float4 v = make_float4(0.f, 0.f, 0.f, 0.f);
        if (gr < N_NODES) v = __ldg(&X4[gr * 16 + f]);
        ((float4*)sA)[r * 16 + f] = v;
    }

    // ---- Gather-mean (fp16 rows, 128B = 1 line/edge) ----
    // 8 lanes per node -> 4 nodes concurrently per warp; 2 edges in flight.
    {
        int g = lane >> 3;                // node group 0..3
        int c = lane & 7;                 // uint4 chunk (8 halfs)
        int nl = w * 4 + g;               // local node 0..63
        int n = row0 + nl;

        float2 a0[4], a1[4];
#pragma unroll
        for (int j = 0; j < 4; j++) {
            a0[j] = make_float2(0.f, 0.f);
            a1[j] = make_float2(0.f, 0.f);
        }
        int deg = 0;
        if (n < N_NODES) {
            int b = __ldg(&g_rowptr[n]);
            int e = __ldg(&g_rowptr[n + 1]);
            deg = e - b;
            int i = b;
            for (; i + 1 < e; i += 2) {
                int s0 = __ldg(&g_esrc[i]);
                int s1 = __ldg(&g_esrc[i + 1]);
                uint4 v0 = __ldg(&H[s0 * 8 + c]);
                uint4 v1 = __ldg(&H[s1 * 8 + c]);
                const __half2* p0 = (const __half2*)&v0;
                const __half2* p1 = (const __half2*)&v1;
#pragma unroll
                for (int j = 0; j < 4; j++) {
                    float2 f0 = __half22float2(p0[j]);
                    float2 f1 = __half22float2(p1[j]);
                    a0[j].x += f0.x; a0[j].y += f0.y;
                    a1[j].x += f1.x; a1[j].y += f1.y;
                }
            }
            if (i < e) {
                int s0 = __ldg(&g_esrc[i]);
                uint4 v0 = __ldg(&H[s0 * 8 + c]);
                const __half2* p0 = (const __half2*)&v0;
#pragma unroll
                for (int j = 0; j < 4; j++) {
                    float2 f0 = __half22float2(p0[j]);
                    a0[j].x += f0.x; a0[j].y += f0.y;
                }
            }
        }
        float inv = 1.0f / (float)(deg > 0 ? deg : 1);
        float s[8];
#pragma unroll
        for (int j = 0; j < 4; j++) {
            s[2 * j]     = (a0[j].x + a1[j].x) * inv;
            s[2 * j + 1] = (a0[j].y + a1[j].y) * inv;
        }
        float4* np = (float4*)(sN + nl * 64 + c * 8);
        np[0] = make_float4(s[0], s[1], s[2], s[3]);
        np[1] = make_float4(s[4], s[5], s[6], s[7]);
    }

    __syncthreads();   // the only CTA-wide sync

    // ---- MAC: 4 rows x 2 cols per thread, W streamed from shared ----
    double accL[4], accH[4];
#pragma unroll
    for (int r = 0; r < 4; r++) { accL[r] = 0.0; accH[r] = 0.0; }

    const double2* wL_s = (const double2*)(sWs + lane * SWP);
    const double2* wH_s = (const double2*)(sWs + (lane + 32) * SWP);
    const double2* wL_n = (const double2*)(sWn + lane * SWP);
    const double2* wH_n = (const double2*)(sWn + (lane + 32) * SWP);
    const double2* tA = (const double2*)sA;   // 16 double2 per row
    const double2* tN = (const double2*)sN;

#pragma unroll
    for (int q = 0; q < 16; q++) {
        double2 w0 = wL_s[q];
        double2 w1 = wH_s[q];
#pragma unroll
        for (int r = 0; r < 4; r++) {
            double2 a = tA[(w * 4 + r) * 16 + q];   // warp-uniform LDS.128
            accL[r] = ffma2(a.x, w0.x, accL[r]);
            accL[r] = ffma2(a.y, w0.y, accL[r]);
            accH[r] = ffma2(a.x, w1.x, accH[r]);
            accH[r] = ffma2(a.y, w1.y, accH[r]);
        }
    }
#pragma unroll
    for (int q = 0; q < 16; q++) {
        double2 w0 = wL_n[q];
        double2 w1 = wH_n[q];
#pragma unroll
        for (int r = 0; r < 4; r++) {
            double2 a = tN[(w * 4 + r) * 16 + q];
            accL[r] = ffma2(a.x, w0.x, accL[r]);
            accL[r] = ffma2(a.y, w0.y, accL[r]);
            accH[r] = ffma2(a.x, w1.x, accH[r]);
            accH[r] = ffma2(a.y, w1.y, accH[r]);
        }
    }

    // ---- Epilogue: bias (+relu); layer 1 also emits the fp16 mirror ----
    const float bv0 = __ldg(&bias[lane]);
    const float bv1 = __ldg(&bias[lane + 32]);
#pragma unroll
    for (int r = 0; r < 4; r++) {
        int gr = row0 + w * 4 + r;
        if (gr < N_NODES) {
            float lo, hi, o0, o1;
            unpack2(accL[r], lo, hi);
            o0 = lo + hi + bv0;
            unpack2(accH[r], lo, hi);
            o1 = lo + hi + bv1;
            if (LAYER1) {
                o0 = fmaxf(o0, 0.f);
                o1 = fmaxf(o1, 0.f);
                g_h1h[gr * 64 + lane]      = __float2half_rn(o0);
                g_h1h[gr * 64 + lane + 32] = __float2half_rn(o1);
            }
            out[gr * 64 + lane]      = o0;
            out[gr * 64 + lane + 32] = o1;
        }
    }
}

// ---------------- Launch ----------------
extern "C" void kernel_launch(void* const* d_in, const int* in_sizes, int n_in,
                              void* d_out, int out_size) {
    const float* in_feat = (const float*)d_in[0];
    const int*   src     = (const int*)d_in[1];
    const int*   dst     = (const int*)d_in[2];
    const float* Ws1     = (const float*)d_in[3];
    const float* Wn1     = (const float*)d_in[4];
    const float* b1      = (const float*)d_in[5];
    const float* Ws2     = (const float*)d_in[6];
    const float* Wn2     = (const float*)d_in[7];
    const float* b2      = (const float*)d_in[8];
    float*       out     = (float*)d_out;

    cudaFuncSetAttribute(sage_fused<true>,
                         cudaFuncAttributeMaxDynamicSharedMemorySize, SMEM_BYTES);
    cudaFuncSetAttribute(sage_fused<false>,
                         cudaFuncAttributeMaxDynamicSharedMemorySize, SMEM_BYTES);

    const int e_blocks    = (N_EDGES + 255) / 256;   // 6250
    const int fuse_blocks = (N_NODES + 63) / 64;     // 1563

    csr_hist_cast<<<e_blocks, 256>>>(dst, (const float4*)in_feat);   // 0
    scan_lookback<<<NB_SCAN, 512>>>();                               // 1
    csr_scatter<<<e_blocks, 256>>>(src, dst);                        // 2
    sage_fused<true><<<fuse_blocks, 512, SMEM_BYTES>>>(in_feat, Ws1, Wn1, b1, nullptr);  // 3 (profiled)
    sage_fused<false><<<fuse_blocks, 512, SMEM_BYTES>>>(nullptr, Ws2, Wn2, b2, out);     // 4
}

// round 13
// speedup vs baseline: 3.4065x; 1.8414x over previous
#include <cuda_runtime.h>
#include <cuda_fp16.h>
#include <cstdint>

#define N_NODES 100000
#define N_EDGES 1600000
#define NB_SCAN 196            // ceil(100000/512)

// Persistent scratch (zero-initialized at module load; scatter re-zeros
// g_degi/g_bsum each call so every graph replay sees the same state).
__device__ __half g_xh [N_NODES * 64];   // fp16 mirror of in_feat
__device__ __half g_h1h[N_NODES * 64];   // fp16 layer-1 output
__device__ int    g_degi[N_NODES];
__device__ int    g_rowptr[N_NODES + 1];
__device__ int    g_cursor[N_NODES];
__device__ int    g_esrc[N_EDGES];
__device__ int    g_bsum[NB_SCAN];

// ---------------- helpers ----------------
__device__ __forceinline__ void st_release(int* p, int v) {
    asm volatile("st.release.gpu.b32 [%0], %1;" :: "l"(p), "r"(v) : "memory");
}
__device__ __forceinline__ int ld_acquire(const int* p) {
    int v;
    asm volatile("ld.acquire.gpu.b32 %0, [%1];" : "=r"(v) : "l"(p) : "memory");
    return v;
}
__device__ __forceinline__ uint32_t s2u(const void* p) {
    return (uint32_t)__cvta_generic_to_shared(p);
}
__device__ __forceinline__ uint32_t h2u(__half2 h) {
    uint32_t u;
    memcpy(&u, &h, 4);
    return u;
}

// ---------------- CSR build ----------------
// (0) histogram + fp16 cast of in_feat.
__global__ void csr_hist_cast(const int* __restrict__ dst,
                              const float4* __restrict__ xin) {
    int e = blockIdx.x * blockDim.x + threadIdx.x;
    if (e < N_EDGES) {
        atomicAdd(&g_degi[dst[e]], 1);
        float4 v = __ldg(&xin[e]);
        __half2* xh2 = (__half2*)g_xh;
        xh2[2 * e]     = __floats2half2_rn(v.x, v.y);
        xh2[2 * e + 1] = __floats2half2_rn(v.z, v.w);
    }
}

// (1) single-pass scan with lookback.
__global__ void scan_lookback() {
    __shared__ int sh[512];
    int t = threadIdx.x, bid = blockIdx.x;
    int idx = bid * 512 + t;
    int v = (idx < N_NODES) ? g_degi[idx] : 0;

    sh[t] = v;
    __syncthreads();
    for (int off = 1; off < 512; off <<= 1) {
        int x = (t >= off) ? sh[t - off] : 0;
        __syncthreads();
        sh[t] += x;
        __syncthreads();
    }
    int incl = sh[t];
    int btot = sh[511];
    if (t == 0) st_release(&g_bsum[bid], btot + 1);

    int pre = 0;
    if (t < bid) {
        int x;
        do { x = ld_acquire(&g_bsum[t]); } while (x == 0);
        pre = x - 1;
    }
    __syncthreads();
    sh[t] = pre;
    __syncthreads();
    for (int off = 256; off > 0; off >>= 1) {
        if (t < off) sh[t] += sh[t + off];
        __syncthreads();
    }
    int excl = incl - v + sh[0];
    if (idx < N_NODES) {
        g_rowptr[idx] = excl;
        g_cursor[idx] = excl;
    }
    if (bid == 0 && t == 0) g_rowptr[N_NODES] = N_EDGES;
}

// (2) scatter + reset degi/bsum for next replay.
__global__ void csr_scatter(const int* __restrict__ src,
                            const int* __restrict__ dst) {
    int e = blockIdx.x * blockDim.x + threadIdx.x;
    if (e < N_EDGES) {
        int p = atomicAdd(&g_cursor[dst[e]], 1);
        g_esrc[p] = src[e];
    }
    if (e < N_NODES) g_degi[e] = 0;
    if (e < NB_SCAN) g_bsum[e] = 0;
}

// ---------------- Fused layer: fp16 gather-mean + HMMA dual GEMM ----------------
// out = act( X @ Ws^T + mean_neigh(X) @ Wn^T + b ), X fp16, fp32 accumulate.
// Tiles in shared (pitch 72 halfs = 144B rows -> conflict-free ldmatrix):
//   sXh self tile, sNh neighbor-mean tile, sWsh/sWnh weights (fp16, [n][k]).
// 16 warps: warp (wm = w&3, wn = w>>2) owns rows wm*16..+15, cols wn*16..+15.
// W stored [n][k] IS B-col-major -> B ldmatrix is NON-trans.
#define PITCH 72

template <bool LAYER1>
__global__ void __launch_bounds__(512)
sage_fused(const float* __restrict__ Wself,
           const float* __restrict__ Wneigh,
           const float* __restrict__ bias,
           float* __restrict__ outp) {
    __shared__ __align__(16) __half sXh[64 * PITCH];
    __shared__ __align__(16) __half sNh[64 * PITCH];
    __shared__ __align__(16) __half sWsh[64 * PITCH];
    __shared__ __align__(16) __half sWnh[64 * PITCH];

    const uint4* H = LAYER1 ? (const uint4*)g_xh : (const uint4*)g_h1h;

    const int tid  = threadIdx.x;
    const int w    = tid >> 5;
    const int lane = tid & 31;
    const int row0 = blockIdx.x * 64;

    // ---- Stage self tile (fp16 rows straight from H) ----
    {
        int r = tid >> 3, c = tid & 7;       // 64 rows x 8 uint4 chunks
        int gr = row0 + r;
        uint4 v = make_uint4(0u, 0u, 0u, 0u);
        if (gr < N_NODES) v = __ldg(&H[gr * 8 + c]);
        *(uint4*)(sXh + r * PITCH + c * 8) = v;
    }

    // ---- Stage weights fp32 -> fp16 ([n][k] layout) ----
    {
        const float4* Ws4 = (const float4*)Wself;
        const float4* Wn4 = (const float4*)Wneigh;
#pragma unroll
        for (int l = 0; l < 2; l++) {
            int i = tid + l * 512;           // 0..1023 float4 index
            int r = i >> 4, f = i & 15;      // row (n), 4-col (k) chunk
            float4 a = __ldg(&Ws4[i]);
            float4 b = __ldg(&Wn4[i]);
            __half2* ps = (__half2*)(sWsh + r * PITCH + f * 4);
            __half2* pn = (__half2*)(sWnh + r * PITCH + f * 4);
            ps[0] = __floats2half2_rn(a.x, a.y);
            ps[1] = __floats2half2_rn(a.z, a.w);
            pn[0] = __floats2half2_rn(b.x, b.y);
            pn[1] = __floats2half2_rn(b.z, b.w);
        }
    }

    // ---- Gather-mean (fp16 rows, 128B = 1 line/edge) -> sNh ----
    // 8 lanes per node -> 4 nodes concurrently per warp; 2 edges in flight.
    {
        int g = lane >> 3;                // node group 0..3
        int c = lane & 7;                 // uint4 chunk (8 halfs)
        int nl = w * 4 + g;               // local node 0..63
        int n = row0 + nl;

        float2 a0[4], a1[4];
#pragma unroll
        for (int j = 0; j < 4; j++) {
            a0[j] = make_float2(0.f, 0.f);
            a1[j] = make_float2(0.f, 0.f);
        }
        int deg = 0;
        if (n < N_NODES) {
            int b = __ldg(&g_rowptr[n]);
            int e = __ldg(&g_rowptr[n + 1]);
            deg = e - b;
            int i = b;
            for (; i + 1 < e; i += 2) {
                int s0 = __ldg(&g_esrc[i]);
                int s1 = __ldg(&g_esrc[i + 1]);
                uint4 v0 = __ldg(&H[s0 * 8 + c]);
                uint4 v1 = __ldg(&H[s1 * 8 + c]);
                const __half2* p0 = (const __half2*)&v0;
                const __half2* p1 = (const __half2*)&v1;
#pragma unroll
                for (int j = 0; j < 4; j++) {
                    float2 f0 = __half22float2(p0[j]);
                    float2 f1 = __half22float2(p1[j]);
                    a0[j].x += f0.x; a0[j].y += f0.y;
                    a1[j].x += f1.x; a1[j].y += f1.y;
                }
            }
            if (i < e) {
                int s0 = __ldg(&g_esrc[i]);
                uint4 v0 = __ldg(&H[s0 * 8 + c]);
                const __half2* p0 = (const __half2*)&v0;
#pragma unroll
                for (int j = 0; j < 4; j++) {
                    float2 f0 = __half22float2(p0[j]);
                    a0[j].x += f0.x; a0[j].y += f0.y;
                }
            }
        }
        float inv = 1.0f / (float)(deg > 0 ? deg : 1);
        uint4 pack;
        pack.x = h2u(__floats2half2_rn((a0[0].x + a1[0].x) * inv,
                                       (a0[0].y + a1[0].y) * inv));
        pack.y = h2u(__floats2half2_rn((a0[1].x + a1[1].x) * inv,
                                       (a0[1].y + a1[1].y) * inv));
        pack.z = h2u(__floats2half2_rn((a0[2].x + a1[2].x) * inv,
                                       (a0[2].y + a1[2].y) * inv));
        pack.w = h2u(__floats2half2_rn((a0[3].x + a1[3].x) * inv,
                                       (a0[3].y + a1[3].y) * inv));
        *(uint4*)(sNh + nl * PITCH + c * 8) = pack;
    }

    __syncthreads();   // the only CTA-wide sync

    // ---- HMMA MAC: both phases accumulate into the same C fragments ----
    const int wm = w & 3, wn = w >> 2;

    // A ldmatrix lane address parts (row fixed, col varies by k-step)
    const int aRow  = wm * 16 + (lane & 7) + ((lane >> 3) & 1) * 8;
    const int aColH = (lane >> 4) * 8;
    // B ldmatrix lane address parts (lanes 0-15 meaningful; others replicate)
    const int bl    = lane & 15;
    const int bRow  = wn * 16 + (bl & 7);       // W row = output col n
    const int bColH = ((bl >> 3) & 1) * 8;      // tile1 = k-offset +8

    float C0[4] = {0.f, 0.f, 0.f, 0.f};
    float C1[4] = {0.f, 0.f, 0.f, 0.f};

#pragma unroll
    for (int ph = 0; ph < 2; ph++) {
        const __half* Xs = ph ? sNh : sXh;
        const __half* Ws = ph ? sWnh : sWsh;
#pragma unroll
        for (int kk = 0; kk < 4; kk++) {
            int k0 = kk * 16;
            uint32_t a0, a1, a2, a3;
            uint32_t aaddr = s2u(Xs + aRow * PITCH + k0 + aColH);
            asm volatile(
                "ldmatrix.sync.aligned.m8n8.x4.shared.b16 {%0,%1,%2,%3}, [%4];"
                : "=r"(a0), "=r"(a1), "=r"(a2), "=r"(a3) : "r"(aaddr));

            // B fragments: W is [n][k] = B col-major -> NON-trans ldmatrix.
            uint32_t b0, b1, b2, b3;
            uint32_t baddr0 = s2u(Ws + bRow * PITCH + k0 + bColH);
            uint32_t baddr1 = s2u(Ws + (bRow + 8) * PITCH + k0 + bColH);
            asm volatile(
                "ldmatrix.sync.aligned.m8n8.x2.shared.b16 {%0,%1}, [%2];"
                : "=r"(b0), "=r"(b1) : "r"(baddr0));
            asm volatile(
                "ldmatrix.sync.aligned.m8n8.x2.shared.b16 {%0,%1}, [%2];"
                : "=r"(b2), "=r"(b3) : "r"(baddr1));

            asm volatile(
                "mma.sync.aligned.m16n8k16.row.col.f32.f16.f16.f32 "
                "{%0,%1,%2,%3}, {%4,%5,%6,%7}, {%8,%9}, {%0,%1,%2,%3};"
                : "+f"(C0[0]), "+f"(C0[1]), "+f"(C0[2]), "+f"(C0[3])
                : "r"(a0), "r"(a1), "r"(a2), "r"(a3), "r"(b0), "r"(b1));
            asm volatile(
                "mma.sync.aligned.m16n8k16.row.col.f32.f16.f16.f32 "
                "{%0,%1,%2,%3}, {%4,%5,%6,%7}, {%8,%9}, {%0,%1,%2,%3};"
                : "+f"(C1[0]), "+f"(C1[1]), "+f"(C1[2]), "+f"(C1[3])
                : "r"(a0), "r"(a1), "r"(a2), "r"(a3), "r"(b2), "r"(b3));
        }
    }

    // ---- Epilogue: bias (+relu). Layer 1 -> fp16 g_h1h; layer 2 -> fp32 out ----
    {
        int g  = lane >> 2;
        int tg = lane & 3;
        int c  = wn * 16 + tg * 2;           // C0 cols c,c+1; C1 cols c+8,c+9
        int gr0 = row0 + wm * 16 + g;
        int gr1 = gr0 + 8;

        float bv0 = __ldg(&bias[c]);
        float bv1 = __ldg(&bias[c + 1]);
        float bv8 = __ldg(&bias[c + 8]);
        float bv9 = __ldg(&bias[c + 9]);

        float o00 = C0[0] + bv0, o01 = C0[1] + bv1;   // row gr0
        float o10 = C0[2] + bv0, o11 = C0[3] + bv1;   // row gr1
        float o08 = C1[0] + bv8, o09 = C1[1] + bv9;   // row gr0 (+8 cols)
        float o18 = C1[2] + bv8, o19 = C1[3] + bv9;   // row gr1

        if (LAYER1) {
            o00 = fmaxf(o00, 0.f); o01 = fmaxf(o01, 0.f);
            o10 = fmaxf(o10, 0.f); o11 = fmaxf(o11, 0.f);
            o08 = fmaxf(o08, 0.f); o09 = fmaxf(o09, 0.f);
            o18 = fmaxf(o18, 0.f); o19 = fmaxf(o19, 0.f);
            __half2* hp = (__half2*)g_h1h;
            if (gr0 < N_NODES) {
                hp[(gr0 * 64 + c) >> 1]     = __floats2half2_rn(o00, o01);
                hp[(gr0 * 64 + c + 8) >> 1] = __floats2half2_rn(o08, o09);
            }
            if (gr1 < N_NODES) {
                hp[(gr1 * 64 + c) >> 1]     = __floats2half2_rn(o10, o11);
                hp[(gr1 * 64 + c + 8) >> 1] = __floats2half2_rn(o18, o19);
            }
        } else {
            if (gr0 < N_NODES) {
                *(float2*)(outp + gr0 * 64 + c)     = make_float2(o00, o01);
                *(float2*)(outp + gr0 * 64 + c + 8) = make_float2(o08, o09);
            }
            if (gr1 < N_NODES) {
                *(float2*)(outp + gr1 * 64 + c)     = make_float2(o10, o11);
                *(float2*)(outp + gr1 * 64 + c + 8) = make_float2(o18, o19);
            }
        }
    }
}

// ---------------- Launch ----------------
extern "C" void kernel_launch(void* const* d_in, const int* in_sizes, int n_in,
                              void* d_out, int out_size) {
    const float* in_feat = (const float*)d_in[0];
    const int*   src     = (const int*)d_in[1];
    const int*   dst     = (const int*)d_in[2];
    const float* Ws1     = (const float*)d_in[3];
    const float* Wn1     = (const float*)d_in[4];
    const float* b1      = (const float*)d_in[5];
    const float* Ws2     = (const float*)d_in[6];
    const float* Wn2     = (const float*)d_in[7];
    const float* b2      = (const float*)d_in[8];
    float*       out     = (float*)d_out;

    const int e_blocks    = (N_EDGES + 255) / 256;   // 6250
    const int fuse_blocks = (N_NODES + 63) / 64;     // 1563

    csr_hist_cast<<<e_blocks, 256>>>(dst, (const float4*)in_feat);   // 0
    scan_lookback<<<NB_SCAN, 512>>>();                               // 1
    csr_scatter<<<e_blocks, 256>>>(src, dst);                        // 2
    sage_fused<true><<<fuse_blocks, 512>>>(Ws1, Wn1, b1, nullptr);   // 3 (profiled)
    sage_fused<false><<<fuse_blocks, 512>>>(Ws2, Wn2, b2, out);      // 4
}